// round 1
// baseline (speedup 1.0000x reference)
#include <cuda_runtime.h>
#include <cstdint>

#define USER_NUM 100000
#define ITEM_NUM 50000
#define DIM      64
#define NEDGE    3200000
#define NB       16384

// ---------------- scratch (device globals; no allocation allowed) ----------
__device__ float g_g1u[USER_NUM * DIM];
__device__ float g_g2u[USER_NUM * DIM];
__device__ float g_g3u[USER_NUM * DIM];
__device__ float g_g1i[ITEM_NUM * DIM];
__device__ float g_g2i[ITEM_NUM * DIM];
__device__ float g_g3i[ITEM_NUM * DIM];
__device__ float g_gcnu[USER_NUM * DIM];
__device__ float g_gcni[ITEM_NUM * DIM];
// accumulators: [0]=bpr_sum, [1]=reg_sum, [2]=lossU dot, [3]=lossI dot
__device__ float g_acc[4];

// ---------------- helpers ---------------------------------------------------
__device__ __forceinline__ void red_v4(float* p, float4 v) {
    asm volatile("red.global.add.v4.f32 [%0], {%1,%2,%3,%4};"
                 :: "l"(p), "f"(v.x), "f"(v.y), "f"(v.z), "f"(v.w)
                 : "memory");
}

// ---------------- zero scratch ----------------------------------------------
__global__ void zero_kernel() {
    const int nU4 = USER_NUM * DIM / 4;
    const int nI4 = ITEM_NUM * DIM / 4;
    float4 z = make_float4(0.f, 0.f, 0.f, 0.f);
    int stride = gridDim.x * blockDim.x;
    for (int i = blockIdx.x * blockDim.x + threadIdx.x; i < nU4; i += stride) {
        reinterpret_cast<float4*>(g_g1u)[i] = z;
        reinterpret_cast<float4*>(g_g2u)[i] = z;
        reinterpret_cast<float4*>(g_g3u)[i] = z;
    }
    for (int i = blockIdx.x * blockDim.x + threadIdx.x; i < nI4; i += stride) {
        reinterpret_cast<float4*>(g_g1i)[i] = z;
        reinterpret_cast<float4*>(g_g2i)[i] = z;
        reinterpret_cast<float4*>(g_g3i)[i] = z;
    }
    if (blockIdx.x == 0 && threadIdx.x < 4) g_acc[threadIdx.x] = 0.f;
}

// ---------------- fused bidirectional SPMM ----------------------------------
// pass 1: g1u[u] += v*item_emb[i]; g1i[i] += v*user_emb[u]
// pass 2: g2u[u] += v*g1i[i];      g2i[i] += v*g1u[u]
// pass 3: g3u[u] += v*g2i[i];      g3i[i] += v*g2u[u]
__global__ void spmm_kernel(const int* __restrict__ eu,
                            const int* __restrict__ ei,
                            const float* __restrict__ ev,
                            const float* __restrict__ xU_ext,
                            const float* __restrict__ xI_ext,
                            int pass) {
    long long t = (long long)blockIdx.x * blockDim.x + threadIdx.x;
    int e = (int)(t >> 4);
    if (e >= NEDGE) return;
    int c = (int)(t & 15);

    const float* xU; const float* xI; float* oU; float* oI;
    if (pass == 1)      { xU = xU_ext; xI = xI_ext; oU = g_g1u; oI = g_g1i; }
    else if (pass == 2) { xU = g_g1u;  xI = g_g1i;  oU = g_g2u; oI = g_g2i; }
    else                { xU = g_g2u;  xI = g_g2i;  oU = g_g3u; oI = g_g3i; }

    int u = eu[e];
    int it = ei[e];
    float v = ev[e];

    float4 a = reinterpret_cast<const float4*>(xI)[(size_t)it * 16 + c];
    float4 b = reinterpret_cast<const float4*>(xU)[(size_t)u  * 16 + c];
    a.x *= v; a.y *= v; a.z *= v; a.w *= v;
    b.x *= v; b.y *= v; b.z *= v; b.w *= v;

    red_v4(oU + (size_t)u  * DIM + c * 4, a);
    red_v4(oI + (size_t)it * DIM + c * 4, b);
}

// ---------------- gcn combine + self-distillation partial --------------------
// side 0 = user, side 1 = item. 1024 threads = 32 warps = 32 rows per block.
__global__ void gcn_kernel(const float* __restrict__ emb,
                           const float* __restrict__ oldE,
                           const float* __restrict__ nvec,
                           int rows, int side) {
    const float* __restrict__ g1  = side ? g_g1i  : g_g1u;
    const float* __restrict__ g2  = side ? g_g2i  : g_g2u;
    const float* __restrict__ g3  = side ? g_g3i  : g_g3u;
    float* __restrict__ gcn       = side ? g_gcni : g_gcnu;
    float* acc = &g_acc[side ? 3 : 2];

    int warp = threadIdx.x >> 5;
    int lane = threadIdx.x & 31;
    int row  = blockIdx.x * 32 + warp;

    __shared__ float sm[32];
    float contrib = 0.f;
    if (row < rows) {
        size_t base = (size_t)row * DIM + lane * 2;
        float2 e  = *reinterpret_cast<const float2*>(emb  + base);
        float2 a1 = *reinterpret_cast<const float2*>(g1   + base);
        float2 a2 = *reinterpret_cast<const float2*>(g2   + base);
        float2 a3 = *reinterpret_cast<const float2*>(g3   + base);
        float gx = e.x + 0.5f * a1.x + (1.f / 3.f) * a2.x + 0.25f * a3.x;
        float gy = e.y + 0.5f * a1.y + (1.f / 3.f) * a2.y + 0.25f * a3.y;
        float2 gv = make_float2(gx, gy);
        *reinterpret_cast<float2*>(gcn + base) = gv;

        float2 o = *reinterpret_cast<const float2*>(oldE + base);
        float dx = o.x - gx, dy = o.y - gy;
        float s = dx * dx + dy * dy;
        #pragma unroll
        for (int off = 16; off; off >>= 1) s += __shfl_xor_sync(0xffffffffu, s, off);
        if (lane == 0) contrib = sqrtf(s) * nvec[row];
    }
    if (lane == 0) sm[warp] = contrib;
    __syncthreads();
    if (warp == 0) {
        float v = sm[lane];
        #pragma unroll
        for (int off = 16; off; off >>= 1) v += __shfl_xor_sync(0xffffffffu, v, off);
        if (lane == 0) atomicAdd(acc, v);
    }
}

// ---------------- BPR loss ----------------------------------------------------
// 256 threads = 8 warps = 8 samples per block.
__global__ void bpr_kernel(const int* __restrict__ user,
                           const int* __restrict__ iti,
                           const int* __restrict__ itj) {
    int warp = threadIdx.x >> 5;
    int lane = threadIdx.x & 31;
    int b = blockIdx.x * 8 + warp;

    float lbpr = 0.f, lreg = 0.f;
    if (b < NB) {
        int uu = user[b], a = iti[b], c = itj[b];
        float2 u2 = reinterpret_cast<const float2*>(g_gcnu + (size_t)uu * DIM)[lane];
        float2 x1 = reinterpret_cast<const float2*>(g_gcni + (size_t)a  * DIM)[lane];
        float2 x2 = reinterpret_cast<const float2*>(g_gcni + (size_t)c  * DIM)[lane];
        float pi = u2.x * x1.x + u2.y * x1.y;
        float pj = u2.x * x2.x + u2.y * x2.y;
        float rg = u2.x * u2.x + u2.y * u2.y
                 + x1.x * x1.x + x1.y * x1.y
                 + x2.x * x2.x + x2.y * x2.y;
        #pragma unroll
        for (int off = 16; off; off >>= 1) {
            pi += __shfl_xor_sync(0xffffffffu, pi, off);
            pj += __shfl_xor_sync(0xffffffffu, pj, off);
            rg += __shfl_xor_sync(0xffffffffu, rg, off);
        }
        if (lane == 0) {
            float x = pi - pj;
            // -log_sigmoid(x) = softplus(-x) = max(-x,0) + log1p(exp(-|x|))
            lbpr = fmaxf(-x, 0.f) + log1pf(expf(-fabsf(x)));
            lreg = rg;
        }
    }
    __shared__ float s1[8], s2[8];
    if (lane == 0) { s1[warp] = lbpr; s2[warp] = lreg; }
    __syncthreads();
    if (threadIdx.x == 0) {
        float a = 0.f, r = 0.f;
        #pragma unroll
        for (int k = 0; k < 8; k++) { a += s1[k]; r += s2[k]; }
        atomicAdd(&g_acc[0], a);
        atomicAdd(&g_acc[1], r);
    }
}

// ---------------- finalize ------------------------------------------------------
__global__ void finalize_kernel(float* __restrict__ out) {
    if (threadIdx.x == 0) {
        float bpr = g_acc[0] / (float)NB;
        float reg = 1e-4f * (g_acc[1] / (float)NB);
        float ls  = g_acc[2] / (float)USER_NUM + g_acc[3] / (float)ITEM_NUM;
        out[0] = bpr + reg;
        out[1] = 100.f * ls;
        out[2] = 1.f;
        out[3] = 1.f;
    }
}

// ---------------- launch ---------------------------------------------------------
extern "C" void kernel_launch(void* const* d_in, const int* in_sizes, int n_in,
                              void* d_out, int out_size) {
    const int*   user     = (const int*)d_in[0];
    const int*   item_i   = (const int*)d_in[1];
    const int*   item_j   = (const int*)d_in[2];
    const int*   edge_u   = (const int*)d_in[3];
    const int*   edge_i   = (const int*)d_in[4];
    const float* edge_val = (const float*)d_in[5];
    const float* user_emb = (const float*)d_in[6];
    const float* item_emb = (const float*)d_in[7];
    const float* old_U    = (const float*)d_in[8];
    const float* old_I    = (const float*)d_in[9];
    const float* n_U      = (const float*)d_in[10];
    const float* n_I      = (const float*)d_in[11];
    float* out = (float*)d_out;

    zero_kernel<<<1024, 256>>>();

    const int spmm_blocks = (int)(((long long)NEDGE * 16 + 255) / 256);
    spmm_kernel<<<spmm_blocks, 256>>>(edge_u, edge_i, edge_val, user_emb, item_emb, 1);
    spmm_kernel<<<spmm_blocks, 256>>>(edge_u, edge_i, edge_val, nullptr,  nullptr,  2);
    spmm_kernel<<<spmm_blocks, 256>>>(edge_u, edge_i, edge_val, nullptr,  nullptr,  3);

    gcn_kernel<<<(USER_NUM + 31) / 32, 1024>>>(user_emb, old_U, n_U, USER_NUM, 0);
    gcn_kernel<<<(ITEM_NUM + 31) / 32, 1024>>>(item_emb, old_I, n_I, ITEM_NUM, 1);

    bpr_kernel<<<(NB + 7) / 8, 256>>>(user, item_i, item_j);

    finalize_kernel<<<1, 32>>>(out);
}

// round 2
// speedup vs baseline: 1.2074x; 1.2074x over previous
#include <cuda_runtime.h>
#include <cstdint>

#define USER_NUM 100000
#define ITEM_NUM 50000
#define DIM      64
#define NEDGE    3200000
#define NB       16384

// ---------------- scratch (device globals; no allocation allowed) ----------
__device__ float g_g1u[USER_NUM * DIM];
__device__ float g_g2u[USER_NUM * DIM];
__device__ float g_gcnu[USER_NUM * DIM];
__device__ float g_g1i[ITEM_NUM * DIM];
__device__ float g_g2i[ITEM_NUM * DIM];
__device__ float g_gcni[ITEM_NUM * DIM];

// CSR structures (rebuilt every call)
__device__ int  g_cnt_u[USER_NUM];
__device__ int  g_cnt_i[ITEM_NUM];
__device__ int  g_rowptr_u[USER_NUM + 1];
__device__ int  g_rowptr_i[ITEM_NUM + 1];
__device__ int  g_head_u[USER_NUM];
__device__ int  g_head_i[ITEM_NUM];
__device__ int2 g_csr_u[NEDGE];   // sorted by user:  (item_idx, val_bits)
__device__ int2 g_csr_i[NEDGE];   // sorted by item:  (user_idx, val_bits)

// accumulators: [0]=bpr_sum, [1]=reg_sum, [2]=lossU dot, [3]=lossI dot
__device__ float g_acc[4];

// ---------------- zero counters ---------------------------------------------
__global__ void zero_kernel() {
    int stride = gridDim.x * blockDim.x;
    for (int i = blockIdx.x * blockDim.x + threadIdx.x; i < USER_NUM; i += stride)
        g_cnt_u[i] = 0;
    for (int i = blockIdx.x * blockDim.x + threadIdx.x; i < ITEM_NUM; i += stride)
        g_cnt_i[i] = 0;
    if (blockIdx.x == 0 && threadIdx.x < 4) g_acc[threadIdx.x] = 0.f;
}

// ---------------- histogram --------------------------------------------------
__global__ void hist_kernel(const int* __restrict__ eu, const int* __restrict__ ei) {
    int e = blockIdx.x * blockDim.x + threadIdx.x;
    if (e >= NEDGE) return;
    atomicAdd(&g_cnt_u[eu[e]], 1);
    atomicAdd(&g_cnt_i[ei[e]], 1);
}

// ---------------- exclusive scan (single block, 1024 threads) -----------------
__global__ void scan_kernel(const int* __restrict__ cnt, int* __restrict__ rowptr,
                            int* __restrict__ head, int n) {
    __shared__ int ssum[1024];
    int t = threadIdx.x;
    int chunk = (n + 1023) >> 10;
    int beg = t * chunk;
    int end = min(beg + chunk, n);
    int s = 0;
    for (int i = beg; i < end; i++) s += cnt[i];
    ssum[t] = s;
    __syncthreads();
    // Hillis-Steele inclusive scan
    for (int off = 1; off < 1024; off <<= 1) {
        int v = (t >= off) ? ssum[t - off] : 0;
        __syncthreads();
        ssum[t] += v;
        __syncthreads();
    }
    int run = (t == 0) ? 0 : ssum[t - 1];
    for (int i = beg; i < end; i++) {
        rowptr[i] = run;
        head[i]   = run;
        run += cnt[i];
    }
    if (beg < n && end == n) rowptr[n] = run;
}

// ---------------- scatter edges into both CSRs --------------------------------
__global__ void scatter_kernel(const int* __restrict__ eu, const int* __restrict__ ei,
                               const float* __restrict__ ev) {
    int e = blockIdx.x * blockDim.x + threadIdx.x;
    if (e >= NEDGE) return;
    int u  = eu[e];
    int it = ei[e];
    int vb = __float_as_int(ev[e]);
    int pu = atomicAdd(&g_head_u[u], 1);
    g_csr_u[pu] = make_int2(it, vb);
    int pi = atomicAdd(&g_head_i[it], 1);
    g_csr_i[pi] = make_int2(u, vb);
}

// ---------------- CSR SPMM: one warp per output row ---------------------------
// out[r] = sum_{e in row r} val(e) * x[col(e)]
__global__ void spmm_csr(const int* __restrict__ rowptr, const int2* __restrict__ csr,
                         const float* __restrict__ x, float* __restrict__ out,
                         int nrows) {
    int warp = (blockIdx.x * blockDim.x + threadIdx.x) >> 5;
    int lane = threadIdx.x & 31;
    if (warp >= nrows) return;
    int beg = __ldg(rowptr + warp);
    int end = __ldg(rowptr + warp + 1);

    float2 acc0 = make_float2(0.f, 0.f);
    float2 acc1 = make_float2(0.f, 0.f);
    int e = beg;
    for (; e + 2 <= end; e += 2) {
        int2 cv0 = __ldg(csr + e);
        int2 cv1 = __ldg(csr + e + 1);
        float v0 = __int_as_float(cv0.y);
        float v1 = __int_as_float(cv1.y);
        float2 x0 = __ldg(reinterpret_cast<const float2*>(x + (size_t)cv0.x * DIM) + lane);
        float2 x1 = __ldg(reinterpret_cast<const float2*>(x + (size_t)cv1.x * DIM) + lane);
        acc0.x += v0 * x0.x; acc0.y += v0 * x0.y;
        acc1.x += v1 * x1.x; acc1.y += v1 * x1.y;
    }
    if (e < end) {
        int2 cv = __ldg(csr + e);
        float v = __int_as_float(cv.y);
        float2 xv = __ldg(reinterpret_cast<const float2*>(x + (size_t)cv.x * DIM) + lane);
        acc0.x += v * xv.x; acc0.y += v * xv.y;
    }
    acc0.x += acc1.x; acc0.y += acc1.y;
    reinterpret_cast<float2*>(out + (size_t)warp * DIM)[lane] = acc0;
}

// ---------------- fused 3rd-hop SPMM + gcn combine + self-distill --------------
// gcn[r] = emb[r] + 0.5*g1[r] + (1/3)*g2[r] + 0.25 * (SPMM row r over xg)
// acc   += ||old[r] - gcn[r]|| * nvec[r]
__global__ void spmm3_fused(const int* __restrict__ rowptr, const int2* __restrict__ csr,
                            const float* __restrict__ xg,
                            const float* __restrict__ emb,
                            const float* __restrict__ g1,
                            const float* __restrict__ g2,
                            const float* __restrict__ oldE,
                            const float* __restrict__ nvec,
                            float* __restrict__ gcn,
                            float* __restrict__ accslot,
                            int nrows) {
    int warpInBlk = threadIdx.x >> 5;
    int warp = (blockIdx.x * blockDim.x + threadIdx.x) >> 5;
    int lane = threadIdx.x & 31;

    __shared__ float sm[8];   // blockDim = 256 -> 8 warps
    float contrib = 0.f;

    if (warp < nrows) {
        int beg = __ldg(rowptr + warp);
        int end = __ldg(rowptr + warp + 1);

        float2 acc0 = make_float2(0.f, 0.f);
        float2 acc1 = make_float2(0.f, 0.f);
        int e = beg;
        for (; e + 2 <= end; e += 2) {
            int2 cv0 = __ldg(csr + e);
            int2 cv1 = __ldg(csr + e + 1);
            float v0 = __int_as_float(cv0.y);
            float v1 = __int_as_float(cv1.y);
            float2 x0 = __ldg(reinterpret_cast<const float2*>(xg + (size_t)cv0.x * DIM) + lane);
            float2 x1 = __ldg(reinterpret_cast<const float2*>(xg + (size_t)cv1.x * DIM) + lane);
            acc0.x += v0 * x0.x; acc0.y += v0 * x0.y;
            acc1.x += v1 * x1.x; acc1.y += v1 * x1.y;
        }
        if (e < end) {
            int2 cv = __ldg(csr + e);
            float v = __int_as_float(cv.y);
            float2 xv = __ldg(reinterpret_cast<const float2*>(xg + (size_t)cv.x * DIM) + lane);
            acc0.x += v * xv.x; acc0.y += v * xv.y;
        }
        float g3x = acc0.x + acc1.x;
        float g3y = acc0.y + acc1.y;

        size_t base = (size_t)warp * DIM;
        float2 ee = __ldg(reinterpret_cast<const float2*>(emb + base) + lane);
        float2 a1 = __ldg(reinterpret_cast<const float2*>(g1  + base) + lane);
        float2 a2 = __ldg(reinterpret_cast<const float2*>(g2  + base) + lane);
        float gx = ee.x + 0.5f * a1.x + (1.f / 3.f) * a2.x + 0.25f * g3x;
        float gy = ee.y + 0.5f * a1.y + (1.f / 3.f) * a2.y + 0.25f * g3y;
        reinterpret_cast<float2*>(gcn + base)[lane] = make_float2(gx, gy);

        float2 o = __ldg(reinterpret_cast<const float2*>(oldE + base) + lane);
        float dx = o.x - gx, dy = o.y - gy;
        float s = dx * dx + dy * dy;
        #pragma unroll
        for (int off = 16; off; off >>= 1) s += __shfl_xor_sync(0xffffffffu, s, off);
        if (lane == 0) contrib = sqrtf(s) * __ldg(nvec + warp);
    }

    if (lane == 0) sm[warpInBlk] = contrib;
    __syncthreads();
    if (threadIdx.x == 0) {
        float v = 0.f;
        #pragma unroll
        for (int k = 0; k < 8; k++) v += sm[k];
        atomicAdd(accslot, v);
    }
}

// ---------------- BPR loss ----------------------------------------------------
__global__ void bpr_kernel(const int* __restrict__ user,
                           const int* __restrict__ iti,
                           const int* __restrict__ itj) {
    int warp = threadIdx.x >> 5;
    int lane = threadIdx.x & 31;
    int b = blockIdx.x * 8 + warp;

    float lbpr = 0.f, lreg = 0.f;
    if (b < NB) {
        int uu = user[b], a = iti[b], c = itj[b];
        float2 u2 = reinterpret_cast<const float2*>(g_gcnu + (size_t)uu * DIM)[lane];
        float2 x1 = reinterpret_cast<const float2*>(g_gcni + (size_t)a  * DIM)[lane];
        float2 x2 = reinterpret_cast<const float2*>(g_gcni + (size_t)c  * DIM)[lane];
        float pi = u2.x * x1.x + u2.y * x1.y;
        float pj = u2.x * x2.x + u2.y * x2.y;
        float rg = u2.x * u2.x + u2.y * u2.y
                 + x1.x * x1.x + x1.y * x1.y
                 + x2.x * x2.x + x2.y * x2.y;
        #pragma unroll
        for (int off = 16; off; off >>= 1) {
            pi += __shfl_xor_sync(0xffffffffu, pi, off);
            pj += __shfl_xor_sync(0xffffffffu, pj, off);
            rg += __shfl_xor_sync(0xffffffffu, rg, off);
        }
        if (lane == 0) {
            float x = pi - pj;
            lbpr = fmaxf(-x, 0.f) + log1pf(expf(-fabsf(x)));
            lreg = rg;
        }
    }
    __shared__ float s1[8], s2[8];
    if (lane == 0) { s1[warp] = lbpr; s2[warp] = lreg; }
    __syncthreads();
    if (threadIdx.x == 0) {
        float a = 0.f, r = 0.f;
        #pragma unroll
        for (int k = 0; k < 8; k++) { a += s1[k]; r += s2[k]; }
        atomicAdd(&g_acc[0], a);
        atomicAdd(&g_acc[1], r);
    }
}

// ---------------- finalize ------------------------------------------------------
__global__ void finalize_kernel(float* __restrict__ out) {
    if (threadIdx.x == 0) {
        float bpr = g_acc[0] / (float)NB;
        float reg = 1e-4f * (g_acc[1] / (float)NB);
        float ls  = g_acc[2] / (float)USER_NUM + g_acc[3] / (float)ITEM_NUM;
        out[0] = bpr + reg;
        out[1] = 100.f * ls;
        out[2] = 1.f;
        out[3] = 1.f;
    }
}

// ---------------- launch ---------------------------------------------------------
extern "C" void kernel_launch(void* const* d_in, const int* in_sizes, int n_in,
                              void* d_out, int out_size) {
    const int*   user     = (const int*)d_in[0];
    const int*   item_i   = (const int*)d_in[1];
    const int*   item_j   = (const int*)d_in[2];
    const int*   edge_u   = (const int*)d_in[3];
    const int*   edge_i   = (const int*)d_in[4];
    const float* edge_val = (const float*)d_in[5];
    const float* user_emb = (const float*)d_in[6];
    const float* item_emb = (const float*)d_in[7];
    const float* old_U    = (const float*)d_in[8];
    const float* old_I    = (const float*)d_in[9];
    const float* n_U      = (const float*)d_in[10];
    const float* n_I      = (const float*)d_in[11];
    float* out = (float*)d_out;

    // device-global symbol addresses (host side must use pointers via cudaGetSymbolAddress?
    // No — __device__ arrays referenced inside kernels directly; for kernel params we
    // take addresses in device code only. All kernels below reference globals directly
    // except spmm_csr/spmm3_fused which need them as parameters.)
    // Use cudaGetSymbolAddress-free approach: small helper kernels take an enum instead.
    // Simpler: obtain raw pointers with cudaGetSymbolAddress is NOT graph-unsafe (host-side,
    // no alloc), but to stay minimal we fetch them once per call.
    static float *p_g1u=nullptr,*p_g2u=nullptr,*p_gcnu=nullptr,
                 *p_g1i=nullptr,*p_g2i=nullptr,*p_gcni=nullptr,*p_acc=nullptr;
    static int  *p_rpu=nullptr,*p_rpi=nullptr,*p_cntu=nullptr,*p_cnti=nullptr,
                *p_hu=nullptr,*p_hi=nullptr;
    static int2 *p_csru=nullptr,*p_csri=nullptr;
    if (!p_g1u) {
        cudaGetSymbolAddress((void**)&p_g1u,  g_g1u);
        cudaGetSymbolAddress((void**)&p_g2u,  g_g2u);
        cudaGetSymbolAddress((void**)&p_gcnu, g_gcnu);
        cudaGetSymbolAddress((void**)&p_g1i,  g_g1i);
        cudaGetSymbolAddress((void**)&p_g2i,  g_g2i);
        cudaGetSymbolAddress((void**)&p_gcni, g_gcni);
        cudaGetSymbolAddress((void**)&p_acc,  g_acc);
        cudaGetSymbolAddress((void**)&p_rpu,  g_rowptr_u);
        cudaGetSymbolAddress((void**)&p_rpi,  g_rowptr_i);
        cudaGetSymbolAddress((void**)&p_cntu, g_cnt_u);
        cudaGetSymbolAddress((void**)&p_cnti, g_cnt_i);
        cudaGetSymbolAddress((void**)&p_hu,   g_head_u);
        cudaGetSymbolAddress((void**)&p_hi,   g_head_i);
        cudaGetSymbolAddress((void**)&p_csru, g_csr_u);
        cudaGetSymbolAddress((void**)&p_csri, g_csr_i);
    }

    const int EB = (NEDGE + 255) / 256;

    zero_kernel<<<512, 256>>>();
    hist_kernel<<<EB, 256>>>(edge_u, edge_i);
    scan_kernel<<<1, 1024>>>(p_cntu, p_rpu, p_hu, USER_NUM);
    scan_kernel<<<1, 1024>>>(p_cnti, p_rpi, p_hi, ITEM_NUM);
    scatter_kernel<<<EB, 256>>>(edge_u, edge_i, edge_val);

    const int UB = (USER_NUM * 32 + 255) / 256;
    const int IB = (ITEM_NUM * 32 + 255) / 256;

    // hop 1
    spmm_csr<<<UB, 256>>>(p_rpu, p_csru, item_emb, p_g1u, USER_NUM);
    spmm_csr<<<IB, 256>>>(p_rpi, p_csri, user_emb, p_g1i, ITEM_NUM);
    // hop 2
    spmm_csr<<<UB, 256>>>(p_rpu, p_csru, p_g1i, p_g2u, USER_NUM);
    spmm_csr<<<IB, 256>>>(p_rpi, p_csri, p_g1u, p_g2i, ITEM_NUM);
    // hop 3 fused with gcn combine + self-distill partials
    spmm3_fused<<<UB, 256>>>(p_rpu, p_csru, p_g2i, user_emb, p_g1u, p_g2u,
                             old_U, n_U, p_gcnu, p_acc + 2, USER_NUM);
    spmm3_fused<<<IB, 256>>>(p_rpi, p_csri, p_g2u, item_emb, p_g1i, p_g2i,
                             old_I, n_I, p_gcni, p_acc + 3, ITEM_NUM);

    bpr_kernel<<<(NB + 7) / 8, 256>>>(user, item_i, item_j);
    finalize_kernel<<<1, 32>>>(out);
}

// round 4
// speedup vs baseline: 1.9735x; 1.6346x over previous
#include <cuda_runtime.h>
#include <cuda_fp16.h>
#include <cstdint>

#define USER_NUM 100000
#define ITEM_NUM 50000
#define DIM      64
#define NEDGE    3200000
#define NB       16384
#define SCAN_CHUNK 4096   // per block in scan: 256 threads x 16

// ---------------- scratch (device globals) ----------------------------------
__device__ __half g_g1u[USER_NUM * DIM];
__device__ __half g_g2u[USER_NUM * DIM];
__device__ __half g_g1i[ITEM_NUM * DIM];
__device__ __half g_g2i[ITEM_NUM * DIM];
__device__ float  g_gcnu[USER_NUM * DIM];
__device__ float  g_gcni[ITEM_NUM * DIM];

__device__ int  g_cnt_u[USER_NUM];
__device__ int  g_cnt_i[ITEM_NUM];
__device__ int  g_rowptr_u[USER_NUM + 1];
__device__ int  g_rowptr_i[ITEM_NUM + 1];
__device__ int  g_head_u[USER_NUM];
__device__ int  g_head_i[ITEM_NUM];
__device__ int  g_bsum_u[32];
__device__ int  g_bsum_i[32];
__device__ int2 g_csr_u[NEDGE];   // (item_idx, val_bits) sorted by user
__device__ int2 g_csr_i[NEDGE];   // (user_idx, val_bits) sorted by item

// [0]=bpr_sum, [1]=reg_sum, [2]=lossU dot, [3]=lossI dot
__device__ float g_acc[4];

// ---------------- zero counters ----------------------------------------------
__global__ void zero_kernel() {
    int stride = gridDim.x * blockDim.x;
    for (int i = blockIdx.x * blockDim.x + threadIdx.x; i < USER_NUM; i += stride)
        g_cnt_u[i] = 0;
    for (int i = blockIdx.x * blockDim.x + threadIdx.x; i < ITEM_NUM; i += stride)
        g_cnt_i[i] = 0;
    if (blockIdx.x == 0 && threadIdx.x < 4) g_acc[threadIdx.x] = 0.f;
}

// ---------------- histogram ----------------------------------------------------
__global__ void hist_kernel(const int* __restrict__ eu, const int* __restrict__ ei) {
    int e = blockIdx.x * blockDim.x + threadIdx.x;
    if (e >= NEDGE) return;
    atomicAdd(&g_cnt_u[eu[e]], 1);
    atomicAdd(&g_cnt_i[ei[e]], 1);
}

// ---------------- 3-phase scan ---------------------------------------------------
__global__ void scan_partial(const int* __restrict__ cnt, int n, int* __restrict__ bsum) {
    __shared__ int sw[8];
    int b = blockIdx.x, t = threadIdx.x;
    int base = b * SCAN_CHUNK;
    int s = 0;
    #pragma unroll
    for (int k = 0; k < 16; k++) {
        int i = base + k * 256 + t;      // coalesced
        if (i < n) s += cnt[i];
    }
    #pragma unroll
    for (int off = 16; off; off >>= 1) s += __shfl_xor_sync(0xffffffffu, s, off);
    if ((t & 31) == 0) sw[t >> 5] = s;
    __syncthreads();
    if (t == 0) {
        int tot = 0;
        #pragma unroll
        for (int k = 0; k < 8; k++) tot += sw[k];
        bsum[b] = tot;
    }
}

// exclusive scan of <=32 block sums in-place; also writes rowptr[n]=NEDGE
__global__ void scan_bsum(int* __restrict__ bsum, int nb, int* __restrict__ rowptr, int n) {
    int lane = threadIdx.x;
    int v = (lane < nb) ? bsum[lane] : 0;
    int incl = v;
    #pragma unroll
    for (int off = 1; off < 32; off <<= 1) {
        int y = __shfl_up_sync(0xffffffffu, incl, off);
        if (lane >= off) incl += y;
    }
    if (lane < nb) bsum[lane] = incl - v;
    if (lane == 0) rowptr[n] = NEDGE;
}

__global__ void scan_final(const int* __restrict__ cnt, int* __restrict__ rowptr,
                           int* __restrict__ head, int n, const int* __restrict__ bsum) {
    int b = blockIdx.x, t = threadIdx.x;
    int base = b * SCAN_CHUNK;
    int idx0 = base + t * 16;
    int v[16];
    int s = 0;
    #pragma unroll
    for (int k = 0; k < 16; k++) {
        int i = idx0 + k;
        v[k] = (i < n) ? cnt[i] : 0;
        s += v[k];
    }
    int lane = t & 31, w = t >> 5;
    int sIncl = s;
    #pragma unroll
    for (int off = 1; off < 32; off <<= 1) {
        int y = __shfl_up_sync(0xffffffffu, sIncl, off);
        if (lane >= off) sIncl += y;
    }
    __shared__ int wsum[8], wpre[8];
    if (lane == 31) wsum[w] = sIncl;
    __syncthreads();
    if (t == 0) {
        int run = 0;
        #pragma unroll
        for (int k = 0; k < 8; k++) { wpre[k] = run; run += wsum[k]; }
    }
    __syncthreads();
    int excl = bsum[b] + wpre[w] + (sIncl - s);
    #pragma unroll
    for (int k = 0; k < 16; k++) {
        int i = idx0 + k;
        if (i < n) { rowptr[i] = excl; head[i] = excl; excl += v[k]; }
    }
}

// ---------------- scatter edges into both CSRs -----------------------------------
__global__ void scatter_kernel(const int* __restrict__ eu, const int* __restrict__ ei,
                               const float* __restrict__ ev) {
    int e = blockIdx.x * blockDim.x + threadIdx.x;
    if (e >= NEDGE) return;
    int u  = eu[e];
    int it = ei[e];
    int vb = __float_as_int(ev[e]);
    int pu = atomicAdd(&g_head_u[u], 1);
    g_csr_u[pu] = make_int2(it, vb);
    int pi = atomicAdd(&g_head_i[it], 1);
    g_csr_i[pi] = make_int2(u, vb);
}

// ---------------- SPMM hop 1: fp32 gather -> half out ------------------------------
// One warp per row; half-warps process alternating edges; lane16 covers 4 cols.
__global__ void spmm_f2h(const int* __restrict__ rowptr, const int2* __restrict__ csr,
                         const float* __restrict__ x, __half* __restrict__ out, int nrows) {
    int row  = (blockIdx.x * blockDim.x + threadIdx.x) >> 5;
    int lane = threadIdx.x & 31;
    int lane16 = lane & 15, hw = lane >> 4;
    if (row >= nrows) return;
    int beg = __ldg(rowptr + row), end = __ldg(rowptr + row + 1);

    float4 acc = make_float4(0.f, 0.f, 0.f, 0.f);
    for (int e = beg + hw; e < end; e += 2) {
        int2 cv = __ldg(csr + e);
        float v = __int_as_float(cv.y);
        float4 xv = __ldg(reinterpret_cast<const float4*>(x) + (size_t)cv.x * 16 + lane16);
        acc.x += v * xv.x; acc.y += v * xv.y; acc.z += v * xv.z; acc.w += v * xv.w;
    }
    acc.x += __shfl_xor_sync(0xffffffffu, acc.x, 16);
    acc.y += __shfl_xor_sync(0xffffffffu, acc.y, 16);
    acc.z += __shfl_xor_sync(0xffffffffu, acc.z, 16);
    acc.w += __shfl_xor_sync(0xffffffffu, acc.w, 16);
    if (lane < 16) {
        __half2 h0 = __floats2half2_rn(acc.x, acc.y);
        __half2 h1 = __floats2half2_rn(acc.z, acc.w);
        uint2 pk;
        pk.x = *reinterpret_cast<unsigned*>(&h0);
        pk.y = *reinterpret_cast<unsigned*>(&h1);
        reinterpret_cast<uint2*>(out + (size_t)row * DIM)[lane16] = pk;
    }
}

// ---------------- SPMM hop 2: half gather -> half out -------------------------------
// NOTE row stride: 64 halves = 16 uint2 per row.
__global__ void spmm_h2h(const int* __restrict__ rowptr, const int2* __restrict__ csr,
                         const __half* __restrict__ x, __half* __restrict__ out, int nrows) {
    int row  = (blockIdx.x * blockDim.x + threadIdx.x) >> 5;
    int lane = threadIdx.x & 31;
    int lane16 = lane & 15, hw = lane >> 4;
    if (row >= nrows) return;
    int beg = __ldg(rowptr + row), end = __ldg(rowptr + row + 1);

    float4 acc = make_float4(0.f, 0.f, 0.f, 0.f);
    for (int e = beg + hw; e < end; e += 2) {
        int2 cv = __ldg(csr + e);
        float v = __int_as_float(cv.y);
        uint2 raw = __ldg(reinterpret_cast<const uint2*>(x) + (size_t)cv.x * 16 + lane16);
        __half2 a = *reinterpret_cast<__half2*>(&raw.x);
        __half2 b = *reinterpret_cast<__half2*>(&raw.y);
        float2 f0 = __half22float2(a), f1 = __half22float2(b);
        acc.x += v * f0.x; acc.y += v * f0.y; acc.z += v * f1.x; acc.w += v * f1.y;
    }
    acc.x += __shfl_xor_sync(0xffffffffu, acc.x, 16);
    acc.y += __shfl_xor_sync(0xffffffffu, acc.y, 16);
    acc.z += __shfl_xor_sync(0xffffffffu, acc.z, 16);
    acc.w += __shfl_xor_sync(0xffffffffu, acc.w, 16);
    if (lane < 16) {
        __half2 h0 = __floats2half2_rn(acc.x, acc.y);
        __half2 h1 = __floats2half2_rn(acc.z, acc.w);
        uint2 pk;
        pk.x = *reinterpret_cast<unsigned*>(&h0);
        pk.y = *reinterpret_cast<unsigned*>(&h1);
        reinterpret_cast<uint2*>(out + (size_t)row * DIM)[lane16] = pk;
    }
}

// ---------------- hop 3 fused: half gather + gcn combine + self-distill -------------
__global__ void spmm3_fused(const int* __restrict__ rowptr, const int2* __restrict__ csr,
                            const __half* __restrict__ xg,
                            const float* __restrict__ emb,
                            const __half* __restrict__ g1,
                            const __half* __restrict__ g2,
                            const float* __restrict__ oldE,
                            const float* __restrict__ nvec,
                            float* __restrict__ gcn,
                            float* __restrict__ accslot,
                            int nrows) {
    int warpInBlk = threadIdx.x >> 5;
    int row  = (blockIdx.x * blockDim.x + threadIdx.x) >> 5;
    int lane = threadIdx.x & 31;
    int lane16 = lane & 15, hw = lane >> 4;

    __shared__ float sm[8];
    float contrib = 0.f;

    if (row < nrows) {
        int beg = __ldg(rowptr + row), end = __ldg(rowptr + row + 1);
        float4 acc = make_float4(0.f, 0.f, 0.f, 0.f);
        for (int e = beg + hw; e < end; e += 2) {
            int2 cv = __ldg(csr + e);
            float v = __int_as_float(cv.y);
            uint2 raw = __ldg(reinterpret_cast<const uint2*>(xg) + (size_t)cv.x * 16 + lane16);
            __half2 a = *reinterpret_cast<__half2*>(&raw.x);
            __half2 b = *reinterpret_cast<__half2*>(&raw.y);
            float2 f0 = __half22float2(a), f1 = __half22float2(b);
            acc.x += v * f0.x; acc.y += v * f0.y; acc.z += v * f1.x; acc.w += v * f1.y;
        }
        acc.x += __shfl_xor_sync(0xffffffffu, acc.x, 16);
        acc.y += __shfl_xor_sync(0xffffffffu, acc.y, 16);
        acc.z += __shfl_xor_sync(0xffffffffu, acc.z, 16);
        acc.w += __shfl_xor_sync(0xffffffffu, acc.w, 16);

        float sq = 0.f;
        if (lane < 16) {
            size_t rb = (size_t)row * DIM;
            float4 ee = __ldg(reinterpret_cast<const float4*>(emb + rb) + lane16);
            uint2 r1 = __ldg(reinterpret_cast<const uint2*>(g1) + (size_t)row * 16 + lane16);
            uint2 r2 = __ldg(reinterpret_cast<const uint2*>(g2) + (size_t)row * 16 + lane16);
            float2 g1a = __half22float2(*reinterpret_cast<__half2*>(&r1.x));
            float2 g1b = __half22float2(*reinterpret_cast<__half2*>(&r1.y));
            float2 g2a = __half22float2(*reinterpret_cast<__half2*>(&r2.x));
            float2 g2b = __half22float2(*reinterpret_cast<__half2*>(&r2.y));
            const float c2 = 1.f / 3.f;
            float4 gv;
            gv.x = ee.x + 0.5f * g1a.x + c2 * g2a.x + 0.25f * acc.x;
            gv.y = ee.y + 0.5f * g1a.y + c2 * g2a.y + 0.25f * acc.y;
            gv.z = ee.z + 0.5f * g1b.x + c2 * g2b.x + 0.25f * acc.z;
            gv.w = ee.w + 0.5f * g1b.y + c2 * g2b.y + 0.25f * acc.w;
            reinterpret_cast<float4*>(gcn + rb)[lane16] = gv;

            float4 ov = __ldg(reinterpret_cast<const float4*>(oldE + rb) + lane16);
            float dx = ov.x - gv.x, dy = ov.y - gv.y, dz = ov.z - gv.z, dw = ov.w - gv.w;
            sq = dx * dx + dy * dy + dz * dz + dw * dw;
        }
        #pragma unroll
        for (int off = 16; off; off >>= 1) sq += __shfl_xor_sync(0xffffffffu, sq, off);
        if (lane == 0) contrib = sqrtf(sq) * __ldg(nvec + row);
    }

    if (lane == 0) sm[warpInBlk] = contrib;
    __syncthreads();
    if (threadIdx.x == 0) {
        float v = 0.f;
        #pragma unroll
        for (int k = 0; k < 8; k++) v += sm[k];
        atomicAdd(accslot, v);
    }
}

// ---------------- BPR loss -----------------------------------------------------------
__global__ void bpr_kernel(const int* __restrict__ user,
                           const int* __restrict__ iti,
                           const int* __restrict__ itj) {
    int warp = threadIdx.x >> 5;
    int lane = threadIdx.x & 31;
    int b = blockIdx.x * 8 + warp;

    float lbpr = 0.f, lreg = 0.f;
    if (b < NB) {
        int uu = user[b], a = iti[b], c = itj[b];
        float2 u2 = reinterpret_cast<const float2*>(g_gcnu + (size_t)uu * DIM)[lane];
        float2 x1 = reinterpret_cast<const float2*>(g_gcni + (size_t)a  * DIM)[lane];
        float2 x2 = reinterpret_cast<const float2*>(g_gcni + (size_t)c  * DIM)[lane];
        float pi = u2.x * x1.x + u2.y * x1.y;
        float pj = u2.x * x2.x + u2.y * x2.y;
        float rg = u2.x * u2.x + u2.y * u2.y
                 + x1.x * x1.x + x1.y * x1.y
                 + x2.x * x2.x + x2.y * x2.y;
        #pragma unroll
        for (int off = 16; off; off >>= 1) {
            pi += __shfl_xor_sync(0xffffffffu, pi, off);
            pj += __shfl_xor_sync(0xffffffffu, pj, off);
            rg += __shfl_xor_sync(0xffffffffu, rg, off);
        }
        if (lane == 0) {
            float x = pi - pj;
            lbpr = fmaxf(-x, 0.f) + log1pf(expf(-fabsf(x)));
            lreg = rg;
        }
    }
    __shared__ float s1[8], s2[8];
    if (lane == 0) { s1[warp] = lbpr; s2[warp] = lreg; }
    __syncthreads();
    if (threadIdx.x == 0) {
        float a = 0.f, r = 0.f;
        #pragma unroll
        for (int k = 0; k < 8; k++) { a += s1[k]; r += s2[k]; }
        atomicAdd(&g_acc[0], a);
        atomicAdd(&g_acc[1], r);
    }
}

// ---------------- finalize --------------------------------------------------------------
__global__ void finalize_kernel(float* __restrict__ out) {
    if (threadIdx.x == 0) {
        float bpr = g_acc[0] / (float)NB;
        float reg = 1e-4f * (g_acc[1] / (float)NB);
        float ls  = g_acc[2] / (float)USER_NUM + g_acc[3] / (float)ITEM_NUM;
        out[0] = bpr + reg;
        out[1] = 100.f * ls;
        out[2] = 1.f;
        out[3] = 1.f;
    }
}

// ---------------- launch ------------------------------------------------------------------
extern "C" void kernel_launch(void* const* d_in, const int* in_sizes, int n_in,
                              void* d_out, int out_size) {
    const int*   user     = (const int*)d_in[0];
    const int*   item_i   = (const int*)d_in[1];
    const int*   item_j   = (const int*)d_in[2];
    const int*   edge_u   = (const int*)d_in[3];
    const int*   edge_i   = (const int*)d_in[4];
    const float* edge_val = (const float*)d_in[5];
    const float* user_emb = (const float*)d_in[6];
    const float* item_emb = (const float*)d_in[7];
    const float* old_U    = (const float*)d_in[8];
    const float* old_I    = (const float*)d_in[9];
    const float* n_U      = (const float*)d_in[10];
    const float* n_I      = (const float*)d_in[11];
    float* out = (float*)d_out;

    static __half *p_g1u=nullptr,*p_g2u=nullptr,*p_g1i=nullptr,*p_g2i=nullptr;
    static float  *p_gcnu=nullptr,*p_gcni=nullptr,*p_acc=nullptr;
    static int    *p_rpu=nullptr,*p_rpi=nullptr,*p_cntu=nullptr,*p_cnti=nullptr,
                  *p_hu=nullptr,*p_hi=nullptr,*p_bsu=nullptr,*p_bsi=nullptr;
    static int2   *p_csru=nullptr,*p_csri=nullptr;
    if (!p_g1u) {
        cudaGetSymbolAddress((void**)&p_g1u,  g_g1u);
        cudaGetSymbolAddress((void**)&p_g2u,  g_g2u);
        cudaGetSymbolAddress((void**)&p_g1i,  g_g1i);
        cudaGetSymbolAddress((void**)&p_g2i,  g_g2i);
        cudaGetSymbolAddress((void**)&p_gcnu, g_gcnu);
        cudaGetSymbolAddress((void**)&p_gcni, g_gcni);
        cudaGetSymbolAddress((void**)&p_acc,  g_acc);
        cudaGetSymbolAddress((void**)&p_rpu,  g_rowptr_u);
        cudaGetSymbolAddress((void**)&p_rpi,  g_rowptr_i);
        cudaGetSymbolAddress((void**)&p_cntu, g_cnt_u);
        cudaGetSymbolAddress((void**)&p_cnti, g_cnt_i);
        cudaGetSymbolAddress((void**)&p_hu,   g_head_u);
        cudaGetSymbolAddress((void**)&p_hi,   g_head_i);
        cudaGetSymbolAddress((void**)&p_bsu,  g_bsum_u);
        cudaGetSymbolAddress((void**)&p_bsi,  g_bsum_i);
        cudaGetSymbolAddress((void**)&p_csru, g_csr_u);
        cudaGetSymbolAddress((void**)&p_csri, g_csr_i);
    }

    const int EB  = (NEDGE + 255) / 256;
    const int NBU = (USER_NUM + SCAN_CHUNK - 1) / SCAN_CHUNK;   // 25
    const int NBI = (ITEM_NUM + SCAN_CHUNK - 1) / SCAN_CHUNK;   // 13

    zero_kernel<<<512, 256>>>();
    hist_kernel<<<EB, 256>>>(edge_u, edge_i);

    scan_partial<<<NBU, 256>>>(p_cntu, USER_NUM, p_bsu);
    scan_partial<<<NBI, 256>>>(p_cnti, ITEM_NUM, p_bsi);
    scan_bsum<<<1, 32>>>(p_bsu, NBU, p_rpu, USER_NUM);
    scan_bsum<<<1, 32>>>(p_bsi, NBI, p_rpi, ITEM_NUM);
    scan_final<<<NBU, 256>>>(p_cntu, p_rpu, p_hu, USER_NUM, p_bsu);
    scan_final<<<NBI, 256>>>(p_cnti, p_rpi, p_hi, ITEM_NUM, p_bsi);

    scatter_kernel<<<EB, 256>>>(edge_u, edge_i, edge_val);

    const int UB = (USER_NUM * 32 + 255) / 256;
    const int IB = (ITEM_NUM * 32 + 255) / 256;

    // hop 1 (fp32 emb -> half)
    spmm_f2h<<<UB, 256>>>(p_rpu, p_csru, item_emb, p_g1u, USER_NUM);
    spmm_f2h<<<IB, 256>>>(p_rpi, p_csri, user_emb, p_g1i, ITEM_NUM);
    // hop 2 (half -> half)
    spmm_h2h<<<UB, 256>>>(p_rpu, p_csru, p_g1i, p_g2u, USER_NUM);
    spmm_h2h<<<IB, 256>>>(p_rpi, p_csri, p_g1u, p_g2i, ITEM_NUM);
    // hop 3 fused with gcn combine + self-distill
    spmm3_fused<<<UB, 256>>>(p_rpu, p_csru, p_g2i, user_emb, p_g1u, p_g2u,
                             old_U, n_U, p_gcnu, p_acc + 2, USER_NUM);
    spmm3_fused<<<IB, 256>>>(p_rpi, p_csri, p_g2u, item_emb, p_g1i, p_g2i,
                             old_I, n_I, p_gcni, p_acc + 3, ITEM_NUM);

    bpr_kernel<<<(NB + 7) / 8, 256>>>(user, item_i, item_j);
    finalize_kernel<<<1, 32>>>(out);
}